// round 8
// baseline (speedup 1.0000x reference)
#include <cuda_runtime.h>
#include <cuda_fp16.h>
#include <cstdint>

// ---------------- problem dims ----------------
#define DIM_M 8192
#define DIM_N 16384
#define DIM_K 4096

#define BM 256
#define BN 128
#define BK 128
#define STAGES 2
#define KT (DIM_K / BK)      // 32
#define MT2 (DIM_M / BM)     // 32
#define NT2 (DIM_N / BN)     // 128
#define GM 16                // supertile: m-tiles per group

#define STAGE_BYTES ((BM * BK + BN * BK) * 2)   // A 64K fp16 + B 32K fp16 = 98304
#define SMEM_TOTAL (STAGES * STAGE_BYTES)       // 196608

// ---------------- device scratch (no allocs allowed) ----------------
__device__ __align__(1024) __half g_x_h[(size_t)DIM_M * DIM_K];   // 64 MB

// ---------------- PTX helpers (plain-compute_103-safe) ----------------
__device__ __forceinline__ uint32_t smem_u32(const void* p) {
    uint32_t a;
    asm("{ .reg .u64 t; cvta.to.shared.u64 t, %1; cvt.u32.u64 %0, t; }" : "=r"(a) : "l"(p));
    return a;
}

__device__ __forceinline__ void cp_async16(uint32_t saddr, const void* gaddr) {
    asm volatile("cp.async.cg.shared.global [%0], [%1], 16;" :: "r"(saddr), "l"(gaddr) : "memory");
}
#define CP_COMMIT()   asm volatile("cp.async.commit_group;" ::: "memory")
#define CP_WAIT_ALL() asm volatile("cp.async.wait_group 0;" ::: "memory")

#define LDMATRIX_X4(r0, r1, r2, r3, addr)                                              \
    asm volatile("ldmatrix.sync.aligned.m8n8.x4.shared.b16 {%0,%1,%2,%3}, [%4];"        \
                 : "=r"(r0), "=r"(r1), "=r"(r2), "=r"(r3) : "r"(addr))

#define MMA_16816(c, a, b)                                                             \
    asm volatile("mma.sync.aligned.m16n8k16.row.col.f32.f16.f16.f32 "                  \
                 "{%0,%1,%2,%3}, {%4,%5,%6,%7}, {%8,%9}, {%0,%1,%2,%3};"               \
                 : "+f"((c)[0]), "+f"((c)[1]), "+f"((c)[2]), "+f"((c)[3])              \
                 : "r"((a)[0]), "r"((a)[1]), "r"((a)[2]), "r"((a)[3]),                 \
                   "r"((b)[0]), "r"((b)[1]))

// ---------------- x conversion kernel (8 elements / thread) ----------------
__global__ void conv_x_f16(const float* __restrict__ x, const float* __restrict__ scale,
                           __half* __restrict__ xh, int n8) {
    int i = blockIdx.x * blockDim.x + threadIdx.x;
    if (i >= n8) return;
    float s = scale[0];
    float4 v0 = reinterpret_cast<const float4*>(x)[2 * i];
    float4 v1 = reinterpret_cast<const float4*>(x)[2 * i + 1];
    union { __half h[8]; uint4 u; } H;
    H.h[0] = __float2half(v0.x * s); H.h[1] = __float2half(v0.y * s);
    H.h[2] = __float2half(v0.z * s); H.h[3] = __float2half(v0.w * s);
    H.h[4] = __float2half(v1.x * s); H.h[5] = __float2half(v1.y * s);
    H.h[6] = __float2half(v1.z * s); H.h[7] = __float2half(v1.w * s);
    reinterpret_cast<uint4*>(xh)[i] = H.u;
}

// ---------------- main GEMM kernel (HMMA fp16 -> fp32, 64x64 warp tiles) ----------------
// A smem: fp16 row = 128 fp16 = 256B = 16 chunks of 16B; phys chunk = c ^ (row & 7)
// B smem: same fp16 layout, but filled in-loop from fp32 W via LDG->cvt->STS.
__global__ void __launch_bounds__(256, 1) hmma_gemm(
    const __half* __restrict__ Ah,   // [M, K] fp16, pre-scaled
    const float* __restrict__ Bw,    // [N, K] fp32 (original W, e4m3-exact values)
    const float* __restrict__ bias,  // [N]
    float* __restrict__ out)         // [M, N]
{
    extern __shared__ char smem[];
    const uint32_t sb = smem_u32(smem);
    const int tid = threadIdx.x;
    const int wid = tid >> 5;
    const int lane = tid & 31;
    const int warp_m = wid & 3;   // 0..3 -> 64-row slabs
    const int warp_n = wid >> 2;  // 0..1 -> 64-col slabs

    // supertile raster: GM m-tiles fastest, then n, then group
    const int bid = blockIdx.x;
    const int mt = (bid / (GM * NT2)) * GM + (bid % GM);
    const int nt = (bid / GM) % NT2;
    const int m0 = mt * BM;
    const int n0 = nt * BN;

    // ---- A loader: one slice = 1/4 of the A stage (4 cp.async / thread) ----
    auto load_A_slice = [&](int s, int kt, int sl) {
        const uint32_t sA = sb + s * STAGE_BYTES;
        const __half* gA = Ah + (size_t)m0 * DIM_K + (size_t)kt * BK;
#pragma unroll
        for (int i = 0; i < 4; i++) {                 // A: slice of 1024 16B-chunks
            int ch = sl * 1024 + i * 256 + tid;
            int row = ch >> 4, c = ch & 15;
            cp_async16(sA + row * 256 + ((c ^ (row & 7)) << 4),
                       gA + (size_t)row * DIM_K + c * 8);
        }
    };

    // ---- B converter: fp32 W -> fp16 swizzled smem, split LDG / STS phases ----
    // One slice = 2 output 16B-chunks per thread (4 x LDG.128 fp32, 16 regs).
    struct BSlice { float4 v[2][2]; };
    auto ldg_B = [&](BSlice& bs, int kt, int sl) {
        const float* gB = Bw + (size_t)n0 * DIM_K + (size_t)kt * BK;
#pragma unroll
        for (int i = 0; i < 2; i++) {
            int ch = sl * 512 + i * 256 + tid;        // 2048 chunks total, 4 slices
            int row = ch >> 4, c = ch & 15;
            const float4* p = reinterpret_cast<const float4*>(gB + (size_t)row * DIM_K + c * 8);
            bs.v[i][0] = p[0];
            bs.v[i][1] = p[1];
        }
    };
    auto sts_B = [&](const BSlice& bs, int s, int sl) {
        const int boff = s * STAGE_BYTES + BM * BK * 2;
#pragma unroll
        for (int i = 0; i < 2; i++) {
            int ch = sl * 512 + i * 256 + tid;
            int row = ch >> 4, c = ch & 15;
            union { __half h[8]; uint4 u; } H;
            H.h[0] = __float2half(bs.v[i][0].x); H.h[1] = __float2half(bs.v[i][0].y);
            H.h[2] = __float2half(bs.v[i][0].z); H.h[3] = __float2half(bs.v[i][0].w);
            H.h[4] = __float2half(bs.v[i][1].x); H.h[5] = __float2half(bs.v[i][1].y);
            H.h[6] = __float2half(bs.v[i][1].z); H.h[7] = __float2half(bs.v[i][1].w);
            *reinterpret_cast<uint4*>(smem + boff + row * 256 + ((c ^ (row & 7)) << 4)) = H.u;
        }
    };

    float acc[4][8][4];
#pragma unroll
    for (int i = 0; i < 4; i++)
#pragma unroll
        for (int j = 0; j < 8; j++)
#pragma unroll
            for (int q = 0; q < 4; q++) acc[i][j][q] = 0.0f;

    // ---- prologue: stage 0 (A via cp.async, B via ldg/cvt/sts) ----
#pragma unroll
    for (int sl = 0; sl < 4; sl++) load_A_slice(0, 0, sl);
    CP_COMMIT();
    {
        BSlice bs;
#pragma unroll
        for (int sl = 0; sl < 4; sl++) { ldg_B(bs, 0, sl); sts_B(bs, 0, sl); }
    }

    BSlice bsA, bsB;   // double-buffered in-flight B slices

    for (int kt = 0; kt < KT; kt++) {
        const int stage = kt & 1;
        CP_WAIT_ALL();        // A group kt complete
        __syncthreads();      // publish stage kt (A cp.async + B STS); prior stage reads done

        const uint32_t sA = sb + stage * STAGE_BYTES;
        const uint32_t sB = sA + BM * BK * 2;
        const bool more = (kt + 1 < KT);
        const int nstage = stage ^ 1;

#pragma unroll
        for (int ks = 0; ks < 8; ks++) {   // 8 x k16 per BK=128 chunk
            // A fragments: 4 m16 tiles (64 rows)
            uint32_t a[4][4];
#pragma unroll
            for (int mi = 0; mi < 4; mi++) {
                int row = warp_m * 64 + mi * 16 + (lane & 15);
                int chunk = ks * 2 + (lane >> 4);
                uint32_t addr = sA + row * 256 + ((chunk ^ (row & 7)) << 4);
                LDMATRIX_X4(a[mi][0], a[mi][1], a[mi][2], a[mi][3], addr);
            }
            // B fragments: 8 n8 tiles (64 cols), 2 per ldmatrix.x4
            uint32_t b[8][2];
#pragma unroll
            for (int p = 0; p < 4; p++) {
                int lane8 = lane & 7;
                int g = lane >> 3;
                int rowb = warp_n * 64 + p * 16 + ((g & 2) ? 8 : 0) + lane8;
                int chunk = ks * 2 + (g & 1);
                uint32_t addr = sB + rowb * 256 + ((chunk ^ (rowb & 7)) << 4);
                LDMATRIX_X4(b[2 * p][0], b[2 * p][1], b[2 * p + 1][0], b[2 * p + 1][1], addr);
            }
#pragma unroll
            for (int mi = 0; mi < 4; mi++)
#pragma unroll
                for (int ni = 0; ni < 8; ni++)
                    MMA_16816(acc[mi][ni], a[mi], b[ni]);

            // next-chunk producers, spread across sub-iterations:
            //  A cp.async slices at ks=0..3; B ldg at ks=0..3 (2-buffered), sts at ks=2..5
            if (more) {
                if (ks < 4) load_A_slice(nstage, kt + 1, ks);
                switch (ks) {
                    case 0: ldg_B(bsA, kt + 1, 0); break;
                    case 1: ldg_B(bsB, kt + 1, 1); break;
                    case 2: sts_B(bsA, nstage, 0); ldg_B(bsA, kt + 1, 2); break;
                    case 3: sts_B(bsB, nstage, 1); ldg_B(bsB, kt + 1, 3); break;
                    case 4: sts_B(bsA, nstage, 2); break;
                    case 5: sts_B(bsB, nstage, 3); break;
                    default: break;
                }
            }
        }
        CP_COMMIT();          // one A group per chunk
    }

    // -------- epilogue: direct register -> gmem (float2), + bias --------
    float2 bv[8];
#pragma unroll
    for (int ni = 0; ni < 8; ni++) {
        int col = n0 + warp_n * 64 + ni * 8 + 2 * (lane & 3);
        bv[ni] = *reinterpret_cast<const float2*>(bias + col);
    }
#pragma unroll
    for (int mi = 0; mi < 4; mi++) {
        size_t r0 = (size_t)(m0 + warp_m * 64 + mi * 16 + (lane >> 2));
        size_t r1 = r0 + 8;
#pragma unroll
        for (int ni = 0; ni < 8; ni++) {
            int col = n0 + warp_n * 64 + ni * 8 + 2 * (lane & 3);
            float2 v0 = make_float2(acc[mi][ni][0] + bv[ni].x, acc[mi][ni][1] + bv[ni].y);
            float2 v1 = make_float2(acc[mi][ni][2] + bv[ni].x, acc[mi][ni][3] + bv[ni].y);
            *reinterpret_cast<float2*>(out + r0 * DIM_N + col) = v0;
            *reinterpret_cast<float2*>(out + r1 * DIM_N + col) = v1;
        }
    }
}

// ---------------- host launch ----------------
extern "C" void kernel_launch(void* const* d_in, const int* in_sizes, int n_in,
                              void* d_out, int out_size) {
    const float* x     = (const float*)d_in[0];
    const float* w     = (const float*)d_in[1];
    const float* scale = (const float*)d_in[2];
    const float* bias  = (const float*)d_in[3];
    float* out = (float*)d_out;

    void* p_xh = nullptr;
    cudaGetSymbolAddress(&p_xh, g_x_h);

    const int n8x = DIM_M * DIM_K / 8;
    conv_x_f16<<<n8x / 256, 256>>>(x, scale, (__half*)p_xh, n8x);

    cudaFuncSetAttribute(hmma_gemm, cudaFuncAttributeMaxDynamicSharedMemorySize, SMEM_TOTAL);
    hmma_gemm<<<MT2 * NT2, 256, SMEM_TOTAL>>>((const __half*)p_xh, w, bias, out);
}

// round 9
// speedup vs baseline: 1.1585x; 1.1585x over previous
#include <cuda_runtime.h>
#include <cuda_fp16.h>
#include <cstdint>

// ---------------- problem dims ----------------
#define DIM_M 8192
#define DIM_N 16384
#define DIM_K 4096

#define BM 256
#define BN 128
#define BK 128
#define STAGES 2
#define KT (DIM_K / BK)      // 32
#define MT2 (DIM_M / BM)     // 32
#define NT2 (DIM_N / BN)     // 128

#define NTHREADS 512

#define STAGE_BYTES ((BM * BK + BN * BK) * 2)   // A 64K + B 32K fp16 = 98304
#define SMEM_TOTAL (STAGES * STAGE_BYTES)       // 196608

// ---------------- device scratch (no allocs allowed) ----------------
__device__ __align__(1024) __half g_x_h[(size_t)DIM_M * DIM_K];   // 64 MB
__device__ __align__(1024) __half g_w_h[(size_t)DIM_N * DIM_K];   // 128 MB

// ---------------- PTX helpers (plain-compute_103-safe) ----------------
__device__ __forceinline__ uint32_t smem_u32(const void* p) {
    uint32_t a;
    asm("{ .reg .u64 t; cvta.to.shared.u64 t, %1; cvt.u32.u64 %0, t; }" : "=r"(a) : "l"(p));
    return a;
}

__device__ __forceinline__ void cp_async16(uint32_t saddr, const void* gaddr) {
    asm volatile("cp.async.cg.shared.global [%0], [%1], 16;" :: "r"(saddr), "l"(gaddr) : "memory");
}
#define CP_COMMIT()   asm volatile("cp.async.commit_group;" ::: "memory")
#define CP_WAIT_ALL() asm volatile("cp.async.wait_group 0;" ::: "memory")

#define LDMATRIX_X4(r0, r1, r2, r3, addr)                                              \
    asm volatile("ldmatrix.sync.aligned.m8n8.x4.shared.b16 {%0,%1,%2,%3}, [%4];"        \
                 : "=r"(r0), "=r"(r1), "=r"(r2), "=r"(r3) : "r"(addr))

#define MMA_16816(c, a, b)                                                             \
    asm volatile("mma.sync.aligned.m16n8k16.row.col.f32.f16.f16.f32 "                  \
                 "{%0,%1,%2,%3}, {%4,%5,%6,%7}, {%8,%9}, {%0,%1,%2,%3};"               \
                 : "+f"((c)[0]), "+f"((c)[1]), "+f"((c)[2]), "+f"((c)[3])              \
                 : "r"((a)[0]), "r"((a)[1]), "r"((a)[2]), "r"((a)[3]),                 \
                   "r"((b)[0]), "r"((b)[1]))

// ---------------- conversion kernels (8 elements / thread) ----------------
__global__ void conv_x_f16(const float* __restrict__ x, const float* __restrict__ scale,
                           __half* __restrict__ xh, int n8) {
    int i = blockIdx.x * blockDim.x + threadIdx.x;
    if (i >= n8) return;
    float s = scale[0];
    float4 v0 = reinterpret_cast<const float4*>(x)[2 * i];
    float4 v1 = reinterpret_cast<const float4*>(x)[2 * i + 1];
    union { __half h[8]; uint4 u; } H;
    H.h[0] = __float2half(v0.x * s); H.h[1] = __float2half(v0.y * s);
    H.h[2] = __float2half(v0.z * s); H.h[3] = __float2half(v0.w * s);
    H.h[4] = __float2half(v1.x * s); H.h[5] = __float2half(v1.y * s);
    H.h[6] = __float2half(v1.z * s); H.h[7] = __float2half(v1.w * s);
    reinterpret_cast<uint4*>(xh)[i] = H.u;
}

__global__ void conv_w_f16(const float* __restrict__ w, __half* __restrict__ wh, int n8) {
    int i = blockIdx.x * blockDim.x + threadIdx.x;
    if (i >= n8) return;
    float4 v0 = reinterpret_cast<const float4*>(w)[2 * i];
    float4 v1 = reinterpret_cast<const float4*>(w)[2 * i + 1];
    union { __half h[8]; uint4 u; } H;
    H.h[0] = __float2half(v0.x); H.h[1] = __float2half(v0.y);
    H.h[2] = __float2half(v0.z); H.h[3] = __float2half(v0.w);
    H.h[4] = __float2half(v1.x); H.h[5] = __float2half(v1.y);
    H.h[6] = __float2half(v1.z); H.h[7] = __float2half(v1.w);
    reinterpret_cast<uint4*>(wh)[i] = H.u;
}

// ---------------- main GEMM kernel (HMMA fp16 -> fp32, 16 warps, 64x32 warp tiles) ----------------
// smem row = 128 fp16 = 256B = 16 chunks of 16B; physical chunk = c ^ (row & 7)
__global__ void __launch_bounds__(NTHREADS, 1) hmma_gemm(
    const __half* __restrict__ Ah,   // [M, K] fp16, pre-scaled
    const __half* __restrict__ Bh,   // [N, K] fp16 (W)
    const float* __restrict__ bias,  // [N]
    float* __restrict__ out)         // [M, N]
{
    extern __shared__ char smem[];
    const uint32_t sb = smem_u32(smem);
    const int tid = threadIdx.x;
    const int wid = tid >> 5;
    const int lane = tid & 31;
    const int warp_m = wid & 3;   // 0..3 -> 64-row slabs
    const int warp_n = wid >> 2;  // 0..3 -> 32-col slabs

    // single-group raster: m fastest (32 m-tiles span full M; A stays L2-resident)
    const int bid = blockIdx.x;
    const int mt = bid % MT2;
    const int nt = bid / MT2;
    const int m0 = mt * BM;
    const int n0 = nt * BN;

    // one slice = 1/4 of a stage's loads: A 2 chunks + B 1 chunk per thread
    auto load_slice = [&](int s, int kt, int sl) {
        const uint32_t sA = sb + s * STAGE_BYTES;
        const uint32_t sB = sA + BM * BK * 2;
        const __half* gA = Ah + (size_t)m0 * DIM_K + (size_t)kt * BK;
        const __half* gB = Bh + (size_t)n0 * DIM_K + (size_t)kt * BK;
#pragma unroll
        for (int i = 0; i < 2; i++) {                 // A: slice of 1024 chunks (4096 total)
            int ch = sl * 1024 + i * NTHREADS + tid;
            int row = ch >> 4, c = ch & 15;
            cp_async16(sA + row * 256 + ((c ^ (row & 7)) << 4),
                       gA + (size_t)row * DIM_K + c * 8);
        }
        {                                             // B: slice of 512 chunks (2048 total)
            int ch = sl * 512 + tid;
            int row = ch >> 4, c = ch & 15;
            cp_async16(sB + row * 256 + ((c ^ (row & 7)) << 4),
                       gB + (size_t)row * DIM_K + c * 8);
        }
    };

    float acc[4][4][4];
#pragma unroll
    for (int i = 0; i < 4; i++)
#pragma unroll
        for (int j = 0; j < 4; j++)
#pragma unroll
            for (int q = 0; q < 4; q++) acc[i][j][q] = 0.0f;

    // prologue: stage 0 fully in flight
#pragma unroll
    for (int sl = 0; sl < 4; sl++) load_slice(0, 0, sl);
    CP_COMMIT();

    for (int kt = 0; kt < KT; kt++) {
        const int stage = kt & 1;
        CP_WAIT_ALL();        // group kt complete
        __syncthreads();      // publish stage kt; all reads of stage kt-1 done

        const uint32_t sA = sb + stage * STAGE_BYTES;
        const uint32_t sB = sA + BM * BK * 2;
        const bool more = (kt + 1 < KT);

#pragma unroll
        for (int ks = 0; ks < 8; ks++) {   // 8 x k16 per BK=128 chunk
            // A fragments: 4 m16 tiles (64 rows)
            uint32_t a[4][4];
#pragma unroll
            for (int mi = 0; mi < 4; mi++) {
                int row = warp_m * 64 + mi * 16 + (lane & 15);
                int chunk = ks * 2 + (lane >> 4);
                uint32_t addr = sA + row * 256 + ((chunk ^ (row & 7)) << 4);
                LDMATRIX_X4(a[mi][0], a[mi][1], a[mi][2], a[mi][3], addr);
            }
            // B fragments: 4 n8 tiles (32 cols), 2 per ldmatrix.x4
            uint32_t b[4][2];
#pragma unroll
            for (int p = 0; p < 2; p++) {
                int lane8 = lane & 7;
                int g = lane >> 3;
                int rowb = warp_n * 32 + p * 16 + ((g & 2) ? 8 : 0) + lane8;
                int chunk = ks * 2 + (g & 1);
                uint32_t addr = sB + rowb * 256 + ((chunk ^ (rowb & 7)) << 4);
                LDMATRIX_X4(b[2 * p][0], b[2 * p][1], b[2 * p + 1][0], b[2 * p + 1][1], addr);
            }
#pragma unroll
            for (int mi = 0; mi < 4; mi++)
#pragma unroll
                for (int ni = 0; ni < 4; ni++)
                    MMA_16816(acc[mi][ni], a[mi], b[ni]);

            // spread next-chunk loads across the first 4 sub-iterations
            if (ks < 4 && more) load_slice(stage ^ 1, kt + 1, ks);
        }
        CP_COMMIT();          // one group per chunk
    }

    // -------- epilogue: direct register -> gmem (float2), + bias --------
    float2 bv[4];
#pragma unroll
    for (int ni = 0; ni < 4; ni++) {
        int col = n0 + warp_n * 32 + ni * 8 + 2 * (lane & 3);
        bv[ni] = *reinterpret_cast<const float2*>(bias + col);
    }
#pragma unroll
    for (int mi = 0; mi < 4; mi++) {
        size_t r0 = (size_t)(m0 + warp_m * 64 + mi * 16 + (lane >> 2));
        size_t r1 = r0 + 8;
#pragma unroll
        for (int ni = 0; ni < 4; ni++) {
            int col = n0 + warp_n * 32 + ni * 8 + 2 * (lane & 3);
            float2 v0 = make_float2(acc[mi][ni][0] + bv[ni].x, acc[mi][ni][1] + bv[ni].y);
            float2 v1 = make_float2(acc[mi][ni][2] + bv[ni].x, acc[mi][ni][3] + bv[ni].y);
            *reinterpret_cast<float2*>(out + r0 * DIM_N + col) = v0;
            *reinterpret_cast<float2*>(out + r1 * DIM_N + col) = v1;
        }
    }
}

// ---------------- host launch ----------------
extern "C" void kernel_launch(void* const* d_in, const int* in_sizes, int n_in,
                              void* d_out, int out_size) {
    const float* x     = (const float*)d_in[0];
    const float* w     = (const float*)d_in[1];
    const float* scale = (const float*)d_in[2];
    const float* bias  = (const float*)d_in[3];
    float* out = (float*)d_out;

    void *p_xh = nullptr, *p_wh = nullptr;
    cudaGetSymbolAddress(&p_xh, g_x_h);
    cudaGetSymbolAddress(&p_wh, g_w_h);

    const int n8x = DIM_M * DIM_K / 8;
    conv_x_f16<<<n8x / 256, 256>>>(x, scale, (__half*)p_xh, n8x);
    const int n8w = (int)((size_t)DIM_N * DIM_K / 8);
    conv_w_f16<<<n8w / 256, 256>>>(w, (__half*)p_wh, n8w);

    cudaFuncSetAttribute(hmma_gemm, cudaFuncAttributeMaxDynamicSharedMemorySize, SMEM_TOTAL);
    hmma_gemm<<<MT2 * NT2, NTHREADS, SMEM_TOTAL>>>((const __half*)p_xh, (const __half*)p_wh, bias, out);
}

// round 10
// speedup vs baseline: 1.2498x; 1.0788x over previous
#include <cuda_runtime.h>
#include <cuda_fp16.h>
#include <cstdint>

// ---------------- problem dims ----------------
#define DIM_M 8192
#define DIM_N 16384
#define DIM_K 4096

#define BM 256
#define BN 128
#define BK 128
#define STAGES 2
#define KT (DIM_K / BK)      // 32
#define MT2 (DIM_M / BM)     // 32
#define NT2 (DIM_N / BN)     // 128
#define GM 16                // supertile: m-tiles per group

#define STAGE_BYTES ((BM * BK + BN * BK) * 2)   // A 64K + B 32K fp16 = 98304
#define SMEM_TOTAL (STAGES * STAGE_BYTES)       // 196608

// ---------------- device scratch (no allocs allowed) ----------------
__device__ __align__(1024) __half g_x_h[(size_t)DIM_M * DIM_K];   // 64 MB
__device__ __align__(1024) __half g_w_h[(size_t)DIM_N * DIM_K];   // 128 MB

// ---------------- PTX helpers (plain-compute_103-safe) ----------------
__device__ __forceinline__ uint32_t smem_u32(const void* p) {
    uint32_t a;
    asm("{ .reg .u64 t; cvta.to.shared.u64 t, %1; cvt.u32.u64 %0, t; }" : "=r"(a) : "l"(p));
    return a;
}

__device__ __forceinline__ void cp_async16(uint32_t saddr, const void* gaddr) {
    asm volatile("cp.async.cg.shared.global [%0], [%1], 16;" :: "r"(saddr), "l"(gaddr) : "memory");
}
#define CP_COMMIT()   asm volatile("cp.async.commit_group;" ::: "memory")
#define CP_WAIT_ALL() asm volatile("cp.async.wait_group 0;" ::: "memory")

#define LDMATRIX_X4(r0, r1, r2, r3, addr)                                              \
    asm volatile("ldmatrix.sync.aligned.m8n8.x4.shared.b16 {%0,%1,%2,%3}, [%4];"        \
                 : "=r"(r0), "=r"(r1), "=r"(r2), "=r"(r3) : "r"(addr))

#define MMA_16816(c, a, b)                                                             \
    asm volatile("mma.sync.aligned.m16n8k16.row.col.f32.f16.f16.f32 "                  \
                 "{%0,%1,%2,%3}, {%4,%5,%6,%7}, {%8,%9}, {%0,%1,%2,%3};"               \
                 : "+f"((c)[0]), "+f"((c)[1]), "+f"((c)[2]), "+f"((c)[3])              \
                 : "r"((a)[0]), "r"((a)[1]), "r"((a)[2]), "r"((a)[3]),                 \
                   "r"((b)[0]), "r"((b)[1]))

// ---------------- merged conversion kernel (8 elements / thread, grid-stride) ----------------
// groups [0, n8x) -> x * scale -> g_x_h ; groups [n8x, n8x+n8w) -> w -> g_w_h
__global__ void conv_all_f16(const float* __restrict__ x, const float* __restrict__ w,
                             const float* __restrict__ scale,
                             __half* __restrict__ xh, __half* __restrict__ wh,
                             int n8x, int n8tot) {
    const float s = scale[0];
    for (int i = blockIdx.x * blockDim.x + threadIdx.x; i < n8tot; i += gridDim.x * blockDim.x) {
        union { __half h[8]; uint4 u; } H;
        if (i < n8x) {
            float4 v0 = reinterpret_cast<const float4*>(x)[2 * (size_t)i];
            float4 v1 = reinterpret_cast<const float4*>(x)[2 * (size_t)i + 1];
            H.h[0] = __float2half(v0.x * s); H.h[1] = __float2half(v0.y * s);
            H.h[2] = __float2half(v0.z * s); H.h[3] = __float2half(v0.w * s);
            H.h[4] = __float2half(v1.x * s); H.h[5] = __float2half(v1.y * s);
            H.h[6] = __float2half(v1.z * s); H.h[7] = __float2half(v1.w * s);
            reinterpret_cast<uint4*>(xh)[i] = H.u;
        } else {
            size_t j = (size_t)(i - n8x);
            float4 v0 = reinterpret_cast<const float4*>(w)[2 * j];
            float4 v1 = reinterpret_cast<const float4*>(w)[2 * j + 1];
            H.h[0] = __float2half(v0.x); H.h[1] = __float2half(v0.y);
            H.h[2] = __float2half(v0.z); H.h[3] = __float2half(v0.w);
            H.h[4] = __float2half(v1.x); H.h[5] = __float2half(v1.y);
            H.h[6] = __float2half(v1.z); H.h[7] = __float2half(v1.w);
            reinterpret_cast<uint4*>(wh)[j] = H.u;
        }
    }
}

// ---------------- main GEMM kernel (HMMA fp16 -> fp32, 64x64 warp tiles) ----------------
// smem row = 128 fp16 = 256B = 16 chunks of 16B; physical chunk = c ^ (row & 7)
__global__ void __launch_bounds__(256, 1) hmma_gemm(
    const __half* __restrict__ Ah,   // [M, K] fp16, pre-scaled
    const __half* __restrict__ Bh,   // [N, K] fp16 (W)
    const float* __restrict__ bias,  // [N]
    float* __restrict__ out)         // [M, N]
{
    extern __shared__ char smem[];
    const uint32_t sb = smem_u32(smem);
    const int tid = threadIdx.x;
    const int wid = tid >> 5;
    const int lane = tid & 31;
    const int warp_m = wid & 3;   // 0..3 -> 64-row slabs
    const int warp_n = wid >> 2;  // 0..1 -> 64-col slabs

    // supertile raster: GM m-tiles fastest, then n, then group
    const int bid = blockIdx.x;
    const int mt = (bid / (GM * NT2)) * GM + (bid % GM);
    const int nt = (bid / GM) % NT2;
    const int m0 = mt * BM;
    const int n0 = nt * BN;

    // one slice = 1/4 of a stage's loads: A 1024 chunks + B 512 chunks => 6 cp.async/thread
    auto load_slice = [&](int s, int kt, int sl) {
        const uint32_t sA = sb + s * STAGE_BYTES;
        const uint32_t sB = sA + BM * BK * 2;
        const __half* gA = Ah + (size_t)m0 * DIM_K + (size_t)kt * BK;
        const __half* gB = Bh + (size_t)n0 * DIM_K + (size_t)kt * BK;
#pragma unroll
        for (int i = 0; i < 4; i++) {                 // A: slice of 1024 chunks
            int ch = sl * 1024 + i * 256 + tid;
            int row = ch >> 4, c = ch & 15;
            cp_async16(sA + row * 256 + ((c ^ (row & 7)) << 4),
                       gA + (size_t)row * DIM_K + c * 8);
        }
#pragma unroll
        for (int i = 0; i < 2; i++) {                 // B: slice of 512 chunks
            int ch = sl * 512 + i * 256 + tid;
            int row = ch >> 4, c = ch & 15;
            cp_async16(sB + row * 256 + ((c ^ (row & 7)) << 4),
                       gB + (size_t)row * DIM_K + c * 8);
        }
    };

    float acc[4][8][4];
#pragma unroll
    for (int i = 0; i < 4; i++)
#pragma unroll
        for (int j = 0; j < 8; j++)
#pragma unroll
            for (int q = 0; q < 4; q++) acc[i][j][q] = 0.0f;

    // prologue: stage 0 fully in flight
#pragma unroll
    for (int sl = 0; sl < 4; sl++) load_slice(0, 0, sl);
    CP_COMMIT();

    for (int kt = 0; kt < KT; kt++) {
        const int stage = kt & 1;
        CP_WAIT_ALL();        // group kt complete
        __syncthreads();      // publish stage kt; all reads of stage kt-1 done

        const uint32_t sA = sb + stage * STAGE_BYTES;
        const uint32_t sB = sA + BM * BK * 2;
        const bool more = (kt + 1 < KT);

#pragma unroll
        for (int ks = 0; ks < 8; ks++) {   // 8 x k16 per BK=128 chunk
            // A fragments: 4 m16 tiles (64 rows)
            uint32_t a[4][4];
#pragma unroll
            for (int mi = 0; mi < 4; mi++) {
                int row = warp_m * 64 + mi * 16 + (lane & 15);
                int chunk = ks * 2 + (lane >> 4);
                uint32_t addr = sA + row * 256 + ((chunk ^ (row & 7)) << 4);
                LDMATRIX_X4(a[mi][0], a[mi][1], a[mi][2], a[mi][3], addr);
            }
            // B fragments: 8 n8 tiles (64 cols), 2 per ldmatrix.x4
            uint32_t b[8][2];
#pragma unroll
            for (int p = 0; p < 4; p++) {
                int lane8 = lane & 7;
                int g = lane >> 3;
                int rowb = warp_n * 64 + p * 16 + ((g & 2) ? 8 : 0) + lane8;
                int chunk = ks * 2 + (g & 1);
                uint32_t addr = sB + rowb * 256 + ((chunk ^ (rowb & 7)) << 4);
                LDMATRIX_X4(b[2 * p][0], b[2 * p][1], b[2 * p + 1][0], b[2 * p + 1][1], addr);
            }
#pragma unroll
            for (int mi = 0; mi < 4; mi++)
#pragma unroll
                for (int ni = 0; ni < 8; ni++)
                    MMA_16816(acc[mi][ni], a[mi], b[ni]);

            // spread next-chunk loads across the first 4 sub-iterations
            if (ks < 4 && more) load_slice(stage ^ 1, kt + 1, ks);
        }
        CP_COMMIT();          // one group per chunk
    }

    // -------- epilogue: direct register -> gmem (float2), + bias --------
    float2 bv[8];
#pragma unroll
    for (int ni = 0; ni < 8; ni++) {
        int col = n0 + warp_n * 64 + ni * 8 + 2 * (lane & 3);
        bv[ni] = *reinterpret_cast<const float2*>(bias + col);
    }
#pragma unroll
    for (int mi = 0; mi < 4; mi++) {
        size_t r0 = (size_t)(m0 + warp_m * 64 + mi * 16 + (lane >> 2));
        size_t r1 = r0 + 8;
#pragma unroll
        for (int ni = 0; ni < 8; ni++) {
            int col = n0 + warp_n * 64 + ni * 8 + 2 * (lane & 3);
            float2 v0 = make_float2(acc[mi][ni][0] + bv[ni].x, acc[mi][ni][1] + bv[ni].y);
            float2 v1 = make_float2(acc[mi][ni][2] + bv[ni].x, acc[mi][ni][3] + bv[ni].y);
            *reinterpret_cast<float2*>(out + r0 * DIM_N + col) = v0;
            *reinterpret_cast<float2*>(out + r1 * DIM_N + col) = v1;
        }
    }
}

// ---------------- host launch ----------------
extern "C" void kernel_launch(void* const* d_in, const int* in_sizes, int n_in,
                              void* d_out, int out_size) {
    const float* x     = (const float*)d_in[0];
    const float* w     = (const float*)d_in[1];
    const float* scale = (const float*)d_in[2];
    const float* bias  = (const float*)d_in[3];
    float* out = (float*)d_out;

    void *p_xh = nullptr, *p_wh = nullptr;
    cudaGetSymbolAddress(&p_xh, g_x_h);
    cudaGetSymbolAddress(&p_wh, g_w_h);

    const int n8x = DIM_M * DIM_K / 8;                      // 4M groups
    const int n8w = (int)((size_t)DIM_N * DIM_K / 8);       // 8M groups
    const int n8tot = n8x + n8w;
    // grid-stride, sized ~4 iterations/thread for good MLP without tail waste
    const int cta = 256;
    int blocks = (n8tot + cta * 4 - 1) / (cta * 4);
    conv_all_f16<<<blocks, cta>>>(x, w, scale, (__half*)p_xh, (__half*)p_wh, n8x, n8tot);

    cudaFuncSetAttribute(hmma_gemm, cudaFuncAttributeMaxDynamicSharedMemorySize, SMEM_TOTAL);
    hmma_gemm<<<MT2 * NT2, 256, SMEM_TOTAL>>>((const __half*)p_xh, (const __half*)p_wh, bias, out);
}